// round 1
// baseline (speedup 1.0000x reference)
#include <cuda_runtime.h>

// Problem constants (match reference)
// STARTS = (0, 752, 184, 568), EMBED=16, r=8, row width 768 floats = 192 float4.
// float4-start per group g (STARTS order): {0, 188, 46, 142}
// Warp layout within a 192-thread row (6 warps of 32):
//   warp 0 -> group 0, base lane 0
//   warp 1 -> group 2, base lane 14   (46 % 32 = 14)
//   warp 4 -> group 3, base lane 14   (142 % 32 = 14)
//   warp 5 -> group 1, base lane 28   (188 % 32 = 28)

#define ROW_F4 192
#define BLK_Y 2
#define NTHREADS (ROW_F4 * BLK_Y)

__global__ __launch_bounds__(NTHREADS) void minireft_kernel(
    const float4* __restrict__ in, float4* __restrict__ out,
    const float* __restrict__ Wp, const float* __restrict__ bp,
    const float* __restrict__ Ws, const float* __restrict__ bs,
    int B)
{
    // Folded edit: out[e] = x[e] + sum_{e'} M[g][e'][e] * x[e'] + c[g][e]
    //   M[g][e'][e] = sum_r (Ws[g][r][e'] - Wp[g][r][e']) * Wp[g][r][e]
    //   c[g][e]     = sum_r (bs[g][r] - bp[g][r]) * Wp[g][r][e]
    __shared__ float sM[4][16][16];
    __shared__ float sC[4][16];

    const int tid = threadIdx.y * ROW_F4 + threadIdx.x;

    for (int idx = tid; idx < 4 * 16 * 16; idx += NTHREADS) {
        int g = idx >> 8, ep = (idx >> 4) & 15, e = idx & 15;
        float acc = 0.f;
        #pragma unroll
        for (int r = 0; r < 8; r++) {
            float wp_ep = Wp[g * 128 + r * 16 + ep];
            float ws_ep = Ws[g * 128 + r * 16 + ep];
            acc += (ws_ep - wp_ep) * Wp[g * 128 + r * 16 + e];
        }
        sM[g][ep][e] = acc;
    }
    for (int idx = tid; idx < 4 * 16; idx += NTHREADS) {
        int g = idx >> 4, e = idx & 15;
        float acc = 0.f;
        #pragma unroll
        for (int r = 0; r < 8; r++)
            acc += (bs[g * 8 + r] - bp[g * 8 + r]) * Wp[g * 128 + r * 16 + e];
        sC[g][e] = acc;
    }
    __syncthreads();

    const int chunk = threadIdx.x;       // 0..191, float4 index within row
    const int wrow  = chunk >> 5;        // warp index within the row (0..5)
    const int lane  = chunk & 31;

    // warp -> (group, base lane) map; uniform across each hardware warp
    int g = -1, base = 0;
    if      (wrow == 0) { g = 0; base = 0;  }
    else if (wrow == 1) { g = 2; base = 14; }
    else if (wrow == 4) { g = 3; base = 14; }
    else if (wrow == 5) { g = 1; base = 28; }

    const long long rstep = (long long)gridDim.x * BLK_Y;
    for (long long row = (long long)blockIdx.x * BLK_Y + threadIdx.y;
         row < B; row += rstep)
    {
        const long long i = row * ROW_F4 + chunk;
        float4 v = in[i];

        if (g >= 0) {
            // Gather this region's 16 channels from the 4 lanes that hold them.
            float x[16];
            #pragma unroll
            for (int k = 0; k < 4; k++) {
                x[4 * k + 0] = __shfl_sync(0xffffffffu, v.x, base + k);
                x[4 * k + 1] = __shfl_sync(0xffffffffu, v.y, base + k);
                x[4 * k + 2] = __shfl_sync(0xffffffffu, v.z, base + k);
                x[4 * k + 3] = __shfl_sync(0xffffffffu, v.w, base + k);
            }
            const int off = lane - base;
            if (off >= 0 && off < 4) {
                const int j = off * 4;
                float d0 = sC[g][j + 0];
                float d1 = sC[g][j + 1];
                float d2 = sC[g][j + 2];
                float d3 = sC[g][j + 3];
                #pragma unroll
                for (int e = 0; e < 16; e++) {
                    const float xe = x[e];
                    d0 += sM[g][e][j + 0] * xe;
                    d1 += sM[g][e][j + 1] * xe;
                    d2 += sM[g][e][j + 2] * xe;
                    d3 += sM[g][e][j + 3] * xe;
                }
                v.x += d0; v.y += d1; v.z += d2; v.w += d3;
            }
        }
        out[i] = v;
    }
}

extern "C" void kernel_launch(void* const* d_in, const int* in_sizes, int n_in,
                              void* d_out, int out_size)
{
    const float* base = (const float*)d_in[0];  // [1, B, 768]
    const float* Wp   = (const float*)d_in[1];  // [4, 8, 16]
    const float* bp   = (const float*)d_in[2];  // [4, 8]
    const float* Ws   = (const float*)d_in[3];  // [4, 8, 16]
    const float* bs   = (const float*)d_in[4];  // [4, 8]
    float* out = (float*)d_out;

    const int B = in_sizes[0] / 768;

    dim3 block(ROW_F4, BLK_Y, 1);
    // grid-stride over rows; ~16 row-iterations per block at B=131072
    int grid = (B + BLK_Y - 1) / BLK_Y;
    if (grid > 4096) grid = 4096;

    minireft_kernel<<<grid, block>>>(
        (const float4*)base, (float4*)out, Wp, bp, Ws, bs, B);
}